// round 6
// baseline (speedup 1.0000x reference)
#include <cuda_runtime.h>
#include <cuda_bf16.h>
#include <cstdint>

#define BB 64
#define TT 512
#define DD 512
#define UU 512
#define NG 2048       // 4*UU
#define MM (BB * TT)  // 32768

// ---------------- device scratch (static: no allocations allowed) ----------------
__device__ float g_zx[(size_t)MM * NG];              // 268 MB: x @ Wk
__device__ __nv_bfloat16 g_xhi[(size_t)MM * DD];     // 32 MB
__device__ __nv_bfloat16 g_xlo[(size_t)MM * DD];     // 32 MB
__device__ __nv_bfloat16 g_wthi[(size_t)NG * DD];    // 2 MB (Wk^T [N][K])
__device__ __nv_bfloat16 g_wtlo[(size_t)NG * DD];    // 2 MB
__device__ __nv_bfloat16 g_wrhi[(size_t)NG * DD];    // 2 MB (Wr^T [N][K])
__device__ __nv_bfloat16 g_wrlo[(size_t)NG * DD];    // 2 MB
__device__ float g_zpart[(size_t)8 * 32 * NG];       // 2 MB split-K partials
__device__ __nv_bfloat16 g_hhi[BB * UU];             // hidden state bf16 hi
__device__ __nv_bfloat16 g_hlo[BB * UU];             // hidden state bf16 lo
__device__ unsigned g_ctrs[64];                      // per-group barrier counters (128B apart)

// ---------------- helpers (arch-agnostic PTX only: compiles via compute_103) -----
__device__ __forceinline__ uint32_t smem_u32(const void* p) {
    uint32_t a;
    asm("{ .reg .u64 t; cvta.to.shared.u64 t, %1; cvt.u32.u64 %0, t; }" : "=r"(a) : "l"(p));
    return a;
}
#define SWZ128(b) ((b) ^ (((b) >> 3) & 0x70))

__device__ __forceinline__ void cp16(uint32_t saddr, const void* gptr) {
    asm volatile("cp.async.cg.shared.global [%0], [%1], 16;" :: "r"(saddr), "l"(gptr) : "memory");
}
#define CP_COMMIT() asm volatile("cp.async.commit_group;" ::: "memory")
#define CP_WAIT1()  asm volatile("cp.async.wait_group 1;" ::: "memory")

__device__ __forceinline__ void ldsm_x4(uint32_t* r, uint32_t addr) {
    asm volatile("ldmatrix.sync.aligned.m8n8.x4.shared.b16 {%0,%1,%2,%3}, [%4];"
                 : "=r"(r[0]), "=r"(r[1]), "=r"(r[2]), "=r"(r[3]) : "r"(addr));
}
__device__ __forceinline__ void ldsm_x2(uint32_t* r, uint32_t addr) {
    asm volatile("ldmatrix.sync.aligned.m8n8.x2.shared.b16 {%0,%1}, [%2];"
                 : "=r"(r[0]), "=r"(r[1]) : "r"(addr));
}
__device__ __forceinline__ void mma_bf16(float* c, const uint32_t* a, const uint32_t* b) {
    asm volatile(
        "mma.sync.aligned.m16n8k16.row.col.f32.bf16.bf16.f32 "
        "{%0,%1,%2,%3}, {%4,%5,%6,%7}, {%8,%9}, {%0,%1,%2,%3};"
        : "+f"(c[0]), "+f"(c[1]), "+f"(c[2]), "+f"(c[3])
        : "r"(a[0]), "r"(a[1]), "r"(a[2]), "r"(a[3]), "r"(b[0]), "r"(b[1]));
}
__device__ __forceinline__ unsigned ldcg_u32(const unsigned* p) {
    unsigned v;
    asm volatile("ld.global.cg.u32 %0, [%1];" : "=r"(v) : "l"(p) : "memory");
    return v;
}

// ---------------- per-group grid barrier: RED arrival, monotonic counter -----------
__device__ __forceinline__ void group_barrier(unsigned* ctr, unsigned tgt) {
    __threadfence();            // release this thread's global writes
    __syncthreads();
    if (threadIdx.x == 0) {
        atomicAdd(ctr, 1u);     // RED (no-return)
        while (ldcg_u32(ctr) < tgt) __nanosleep(32);
    }
    __syncthreads();
}

// =======================================================================
// Prep 1: x fp32 -> bf16 hi/lo split, same [M, K] row-major layout.
// =======================================================================
__global__ __launch_bounds__(256) void prep_x(const float* __restrict__ x) {
    size_t i = (size_t)blockIdx.x * 256 + threadIdx.x;  // float4 index
    const size_t n4 = (size_t)MM * DD / 4;
    if (i >= n4) return;
    float4 v = ((const float4*)x)[i];
    __nv_bfloat16 h0 = __float2bfloat16(v.x), h1 = __float2bfloat16(v.y);
    __nv_bfloat16 h2 = __float2bfloat16(v.z), h3 = __float2bfloat16(v.w);
    __nv_bfloat16 l0 = __float2bfloat16(v.x - __bfloat162float(h0));
    __nv_bfloat16 l1 = __float2bfloat16(v.y - __bfloat162float(h1));
    __nv_bfloat16 l2 = __float2bfloat16(v.z - __bfloat162float(h2));
    __nv_bfloat16 l3 = __float2bfloat16(v.w - __bfloat162float(h3));
    ((__nv_bfloat162*)g_xhi)[2 * i]     = __nv_bfloat162(h0, h1);
    ((__nv_bfloat162*)g_xhi)[2 * i + 1] = __nv_bfloat162(h2, h3);
    ((__nv_bfloat162*)g_xlo)[2 * i]     = __nv_bfloat162(l0, l1);
    ((__nv_bfloat162*)g_xlo)[2 * i + 1] = __nv_bfloat162(l2, l3);
}

// =======================================================================
// Prep 2: W [K=512][N=2048] fp32 -> transposed bf16 hi/lo [N][K].
// dhi/dlo are DEVICE-RESOLVED pointers (cudaGetSymbolAddress on host).
// =======================================================================
__global__ __launch_bounds__(256) void prep_wt(const float* __restrict__ W,
                                               __nv_bfloat16* __restrict__ dhi,
                                               __nv_bfloat16* __restrict__ dlo) {
    __shared__ float s[32][33];
    const int n0 = blockIdx.x * 32;
    const int k0 = blockIdx.y * 32;
    const int tx = threadIdx.x & 31;
    const int ty = threadIdx.x >> 5;
#pragma unroll
    for (int j = 0; j < 32; j += 8)
        s[ty + j][tx] = W[(size_t)(k0 + ty + j) * NG + n0 + tx];
    __syncthreads();
#pragma unroll
    for (int j = 0; j < 32; j += 8) {
        float v = s[tx][ty + j];
        __nv_bfloat16 h = __float2bfloat16(v);
        __nv_bfloat16 l = __float2bfloat16(v - __bfloat162float(h));
        size_t o = (size_t)(n0 + ty + j) * DD + k0 + tx;
        dhi[o] = h;
        dlo[o] = l;
    }
}

// =======================================================================
// Phase 1 GEMM (mma.sync bf16 x3): zx = x @ Wk   (validated R3/R5)
// =======================================================================
#define STAGE_BYTES 65536
#define SA_HI 0
#define SA_LO 16384
#define SB_HI 32768
#define SB_LO 49152
#define GEMM_SMEM (2 * STAGE_BYTES)

__device__ __forceinline__ void load_stage(uint32_t sbase, int m0, int n0, int kc, int tid) {
    const uint32_t ksrc = (uint32_t)kc * 128;
    const char* pxh = (const char*)g_xhi;
    const char* pxl = (const char*)g_xlo;
    const char* pwh = (const char*)g_wthi;
    const char* pwl = (const char*)g_wtlo;
#pragma unroll
    for (int i = 0; i < 4; i++) {
        int idx = i * 256 + tid;
        int row = idx >> 3;
        uint32_t q = (uint32_t)(idx & 7) * 16;
        uint32_t sw = SWZ128((uint32_t)row * 128 + q);
        size_t asrc = (size_t)(m0 + row) * 1024 + ksrc + q;
        size_t bsrc = (size_t)(n0 + row) * 1024 + ksrc + q;
        cp16(sbase + SA_HI + sw, pxh + asrc);
        cp16(sbase + SA_LO + sw, pxl + asrc);
        cp16(sbase + SB_HI + sw, pwh + bsrc);
        cp16(sbase + SB_LO + sw, pwl + bsrc);
    }
}

__global__ __launch_bounds__(256) void gemm_zx_mma() {
    extern __shared__ __align__(1024) char smem[];
    const uint32_t sb = smem_u32(smem);
    const int tid = threadIdx.x;
    const int wid = tid >> 5, lid = tid & 31;
    const int n0 = blockIdx.x * 128, m0 = blockIdx.y * 128;
    const int wm = wid & 1;
    const int wn = wid >> 1;

    float acc[4][4][4];
#pragma unroll
    for (int mf = 0; mf < 4; mf++)
#pragma unroll
        for (int nf = 0; nf < 4; nf++)
#pragma unroll
            for (int e = 0; e < 4; e++) acc[mf][nf][e] = 0.0f;

    load_stage(sb, m0, n0, 0, tid);
    CP_COMMIT();

    for (int kc = 0; kc < 8; kc++) {
        if (kc < 7) load_stage(sb + ((kc + 1) & 1) * STAGE_BYTES, m0, n0, kc + 1, tid);
        CP_COMMIT();
        CP_WAIT1();
        __syncthreads();

        const uint32_t st = sb + (kc & 1) * STAGE_BYTES;
        const int la = lid & 15;
        const uint32_t a_koff = (uint32_t)(lid >> 4) * 16;
        const uint32_t b_koff = (uint32_t)((la >> 3) & 1) * 16;

#pragma unroll
        for (int k16 = 0; k16 < 4; k16++) {
            const uint32_t kb = (uint32_t)k16 * 32;
            uint32_t ah[4][4], al[4][4];
#pragma unroll
            for (int mf = 0; mf < 4; mf++) {
                uint32_t row = (uint32_t)(wm * 64 + mf * 16 + la);
                uint32_t sw = SWZ128(row * 128 + kb + a_koff);
                ldsm_x4(ah[mf], st + SA_HI + sw);
                ldsm_x4(al[mf], st + SA_LO + sw);
            }
            uint32_t bh[4][2], bl[4][2];
#pragma unroll
            for (int nf = 0; nf < 4; nf++) {
                uint32_t nrow = (uint32_t)(wn * 32 + nf * 8 + (la & 7));
                uint32_t sw = SWZ128(nrow * 128 + kb + b_koff);
                ldsm_x2(bh[nf], st + SB_HI + sw);
                ldsm_x2(bl[nf], st + SB_LO + sw);
            }
#pragma unroll
            for (int mf = 0; mf < 4; mf++)
#pragma unroll
                for (int nf = 0; nf < 4; nf++) {
                    mma_bf16(acc[mf][nf], ah[mf], bh[nf]);
                    mma_bf16(acc[mf][nf], ah[mf], bl[nf]);
                    mma_bf16(acc[mf][nf], al[mf], bh[nf]);
                }
        }
        __syncthreads();
    }

    const int g = lid >> 2, tig = lid & 3;
#pragma unroll
    for (int mf = 0; mf < 4; mf++) {
        int row = m0 + wm * 64 + mf * 16 + g;
        float* b0 = g_zx + (size_t)row * NG + n0 + wn * 32;
        float* b1 = b0 + (size_t)8 * NG;
#pragma unroll
        for (int nf = 0; nf < 4; nf++) {
            *(float2*)(b0 + nf * 8 + 2 * tig) = make_float2(acc[mf][nf][0], acc[mf][nf][1]);
            *(float2*)(b1 + nf * 8 + 2 * tig) = make_float2(acc[mf][nf][2], acc[mf][nf][3]);
        }
    }
}

// =======================================================================
// Phase 2: persistent LSTM recurrence — tensorized, 2 independent batch
// groups of 64 CTAs (32 batches each) with separate barrier counters.
// CTA (grp, cg 0..15, ks 0..3): cols [cg*128,+128), K slice [ks*128,+128).
// Wr slice (128 cols x 128 K, hi/lo) in smem as two 128B-row half-K tiles;
// B-fragments register-resident for all 512 steps; c in a register;
// zx(t) prefetched at step start.
// =======================================================================
#define R_WHI 0
#define R_WLO 32768
#define R_HHI 65536
#define R_HLO 73728
#define REC_SMEM 81920

__global__ __launch_bounds__(256) void lstm_recur(const float* __restrict__ bias,
                                                  float* __restrict__ out) {
    extern __shared__ __align__(1024) char rsm[];
    const uint32_t sb = smem_u32(rsm);
    const int tid = threadIdx.x;
    const int wid = tid >> 5, lid = tid & 31;
    const int blk = blockIdx.x;
    const int grp = blk >> 6;         // 0..1 batch group (32 batches)
    const int lblk = blk & 63;
    const int cg = lblk >> 2;         // 0..15 col group (128 cols)
    const int ks = lblk & 3;          // 0..3  K slice (128 K)
    const int wn = wid;               // 8 warps x 16 cols
    unsigned* ctr = &g_ctrs[grp * 32];

    // ---- load persistent Wr^T slice: [khalf(2)][col(128)] rows of 128B ----
#pragma unroll
    for (int r = 0; r < 8; r++) {
        int i = r * 256 + tid;          // 0..2047
        int trow = i >> 3;              // 0..255 = khalf*128 + col
        uint32_t q = (uint32_t)(i & 7) * 16;
        int khalf = trow >> 7, col = trow & 127;
        uint32_t sw = SWZ128((uint32_t)trow * 128 + q);
        size_t src = (size_t)(cg * 128 + col) * 1024 + (size_t)ks * 256 + (size_t)khalf * 128 + q;
        *(float4*)(rsm + R_WHI + sw) = *(const float4*)((const char*)g_wrhi + src);
        *(float4*)(rsm + R_WLO + sw) = *(const float4*)((const char*)g_wrlo + src);
    }

    // ---- phase-B ownership: thread -> (b, u) within group ----
    const int lgid = lblk * 256 + tid;   // 0..16383 = 32b x 512u
    const int b_l = lgid >> 9;           // 0..31
    const int ub = lgid & 511;
    const int bglob = grp * 32 + b_l;
    const int hidx = bglob * UU + ub;
    g_hhi[hidx] = __float2bfloat16(0.0f);
    g_hlo[hidx] = __float2bfloat16(0.0f);
    float c_reg = 0.0f;
    __syncthreads();

    // ---- preload B fragments (Wr) into registers for all 512 steps ----
    const int la = lid & 15;
    const uint32_t a_koff = (uint32_t)(lid >> 4) * 16;
    const uint32_t b_koff = (uint32_t)((la >> 3) & 1) * 16;
    uint32_t bhfr[2][8][2], blfr[2][8][2];   // [nf][k16][2]
#pragma unroll
    for (int nf = 0; nf < 2; nf++)
#pragma unroll
        for (int k16 = 0; k16 < 8; k16++) {
            int khalf = k16 >> 2;
            uint32_t kb = (uint32_t)(k16 & 3) * 32;
            uint32_t nrow = (uint32_t)(khalf * 128 + wn * 16 + nf * 8 + (la & 7));
            uint32_t sw = SWZ128(nrow * 128 + kb + b_koff);
            ldsm_x2(bhfr[nf][k16], sb + R_WHI + sw);
            ldsm_x2(blfr[nf][k16], sb + R_WLO + sw);
        }

    unsigned tgt = 0;
    tgt += 64; group_barrier(ctr, tgt);   // group h zeros visible

    const int g = lid >> 2, tig = lid & 3;
    const char* hhi_base = (const char*)g_hhi + (size_t)grp * 32 * 1024;  // 32 batches x 1024B
    const char* hlo_base = (const char*)g_hlo + (size_t)grp * 32 * 1024;

    for (int t = 0; t < TT; t++) {
        // ---- prefetch zx(t) for phase B (independent of everything) ----
        const float* zxp = &g_zx[(size_t)(bglob * TT + t) * NG];
        float zx0 = __ldg(zxp + ub);
        float zx1 = __ldg(zxp + 512 + ub);
        float zx2 = __ldg(zxp + 1024 + ub);
        float zx3 = __ldg(zxp + 1536 + ub);

        // ---- stage h slice: [khalf(2)][b(32)] rows of 128B, hi/lo ----
#pragma unroll
        for (int r = 0; r < 2; r++) {
            int i = r * 256 + tid;        // 0..511
            int trow = i >> 3;            // 0..63 = khalf*32 + b
            uint32_t q = (uint32_t)(i & 7) * 16;
            int khalf = trow >> 5, b = trow & 31;
            uint32_t sw = SWZ128((uint32_t)trow * 128 + q);
            size_t src = (size_t)b * 1024 + (size_t)ks * 256 + (size_t)khalf * 128 + q;
            *(float4*)(rsm + R_HHI + sw) = __ldcg((const float4*)(hhi_base + src));
            *(float4*)(rsm + R_HLO + sw) = __ldcg((const float4*)(hlo_base + src));
        }
        __syncthreads();

        float acc[2][2][4];
#pragma unroll
        for (int mf = 0; mf < 2; mf++)
#pragma unroll
            for (int nf = 0; nf < 2; nf++)
#pragma unroll
                for (int e = 0; e < 4; e++) acc[mf][nf][e] = 0.0f;

#pragma unroll
        for (int k16 = 0; k16 < 8; k16++) {
            int khalf = k16 >> 2;
            uint32_t kb = (uint32_t)(k16 & 3) * 32;
            uint32_t ah[2][4], al[2][4];
#pragma unroll
            for (int mf = 0; mf < 2; mf++) {
                uint32_t row = (uint32_t)(khalf * 32 + mf * 16 + la);
                uint32_t sw = SWZ128(row * 128 + kb + a_koff);
                ldsm_x4(ah[mf], sb + R_HHI + sw);
                ldsm_x4(al[mf], sb + R_HLO + sw);
            }
#pragma unroll
            for (int mf = 0; mf < 2; mf++)
#pragma unroll
                for (int nf = 0; nf < 2; nf++) {
                    mma_bf16(acc[mf][nf], ah[mf], bhfr[nf][k16]);
                    mma_bf16(acc[mf][nf], ah[mf], blfr[nf][k16]);
                    mma_bf16(acc[mf][nf], al[mf], bhfr[nf][k16]);
                }
        }

        // ---- write split-K partials: zpart[(grp*4+ks)*32 + b][col] ----
#pragma unroll
        for (int mf = 0; mf < 2; mf++) {
            int br = mf * 16 + g;
#pragma unroll
            for (int nf = 0; nf < 2; nf++) {
                int col = cg * 128 + wn * 16 + nf * 8 + 2 * tig;
                float* z0 = &g_zpart[((size_t)((grp * 4 + ks) * 32) + br) * NG + col];
                float* z1 = z0 + (size_t)8 * NG;
                *(float2*)z0 = make_float2(acc[mf][nf][0], acc[mf][nf][1]);
                *(float2*)z1 = make_float2(acc[mf][nf][2], acc[mf][nf][3]);
            }
        }
        tgt += 64; group_barrier(ctr, tgt);

        // ---- phase B: reduce 4 partials + gates ----
        {
            float z0 = bias[ub]        + zx0;
            float z1 = bias[512 + ub]  + zx1;
            float z2 = bias[1024 + ub] + zx2;
            float z3 = bias[1536 + ub] + zx3;
#pragma unroll
            for (int s = 0; s < 4; s++) {
                const float* zp = &g_zpart[((size_t)((grp * 4 + s) * 32) + b_l) * NG];
                z0 += __ldcg(zp + ub);
                z1 += __ldcg(zp + 512 + ub);
                z2 += __ldcg(zp + 1024 + ub);
                z3 += __ldcg(zp + 1536 + ub);
            }
            float ig = 1.0f / (1.0f + expf(-z0));
            float fg = 1.0f / (1.0f + expf(-z1));
            float gg = tanhf(z2);
            float og = 1.0f / (1.0f + expf(-z3));
            float cv = fg * c_reg + ig * gg;
            c_reg = cv;
            float hv = og * tanhf(cv);
            __nv_bfloat16 hh = __float2bfloat16(hv);
            g_hhi[hidx] = hh;
            g_hlo[hidx] = __float2bfloat16(hv - __bfloat162float(hh));
            if (t == TT - 1) out[hidx] = hv;
        }
        tgt += 64; group_barrier(ctr, tgt);
    }
}

// =======================================================================
extern "C" void kernel_launch(void* const* d_in, const int* in_sizes, int n_in,
                              void* d_out, int out_size) {
    const float* x  = (const float*)d_in[0];
    const float* Wk = (const float*)d_in[1];
    const float* Wr = (const float*)d_in[2];
    const float* b  = (const float*)d_in[3];
    float* out = (float*)d_out;

    cudaFuncSetAttribute(gemm_zx_mma, cudaFuncAttributeMaxDynamicSharedMemorySize, GEMM_SMEM);
    cudaFuncSetAttribute(lstm_recur, cudaFuncAttributeMaxDynamicSharedMemorySize, REC_SMEM);

    // Resolve DEVICE addresses of __device__ symbols on the host.
    void* ctr_ptr = nullptr;
    void *wthi, *wtlo, *wrhi, *wrlo;
    cudaGetSymbolAddress(&ctr_ptr, g_ctrs);
    cudaGetSymbolAddress(&wthi, g_wthi);
    cudaGetSymbolAddress(&wtlo, g_wtlo);
    cudaGetSymbolAddress(&wrhi, g_wrhi);
    cudaGetSymbolAddress(&wrlo, g_wrlo);

    cudaMemsetAsync(ctr_ptr, 0, 64 * sizeof(unsigned));   // graph-capturable

    prep_x<<<(MM * DD / 4 + 255) / 256, 256>>>(x);
    prep_wt<<<dim3(NG / 32, DD / 32), 256>>>(Wk, (__nv_bfloat16*)wthi, (__nv_bfloat16*)wtlo);
    prep_wt<<<dim3(NG / 32, DD / 32), 256>>>(Wr, (__nv_bfloat16*)wrhi, (__nv_bfloat16*)wrlo);
    gemm_zx_mma<<<dim3(NG / 128, MM / 128), 256, GEMM_SMEM>>>();
    lstm_recur<<<128, 256, REC_SMEM>>>(b, out);
}

// round 7
// speedup vs baseline: 1.2246x; 1.2246x over previous
#include <cuda_runtime.h>
#include <cuda_bf16.h>
#include <cstdint>

#define BB 64
#define TT 512
#define DD 512
#define UU 512
#define NG 2048       // 4*UU
#define MM (BB * TT)  // 32768

// ---------------- device scratch (static: no allocations allowed) ----------------
__device__ float g_zx[(size_t)MM * NG];              // 268 MB: x @ Wk
__device__ __nv_bfloat16 g_xhi[(size_t)MM * DD];     // 32 MB
__device__ __nv_bfloat16 g_xlo[(size_t)MM * DD];     // 32 MB
__device__ __nv_bfloat16 g_wthi[(size_t)NG * DD];    // 2 MB (Wk^T [N][K])
__device__ __nv_bfloat16 g_wtlo[(size_t)NG * DD];    // 2 MB
__device__ __nv_bfloat16 g_wrhi[(size_t)NG * DD];    // 2 MB (Wr^T [N][K])
__device__ __nv_bfloat16 g_wrlo[(size_t)NG * DD];    // 2 MB
__device__ float g_zpart[(size_t)8 * BB * NG];       // 4 MB split-K partials
__device__ __nv_bfloat16 g_hhi[BB * UU];             // hidden state bf16 hi
__device__ __nv_bfloat16 g_hlo[BB * UU];             // hidden state bf16 lo
__device__ unsigned g_ctr;                            // monotonic barrier counter

// ---------------- helpers (arch-agnostic PTX only: compiles via compute_103) -----
__device__ __forceinline__ uint32_t smem_u32(const void* p) {
    uint32_t a;
    asm("{ .reg .u64 t; cvta.to.shared.u64 t, %1; cvt.u32.u64 %0, t; }" : "=r"(a) : "l"(p));
    return a;
}
#define SWZ128(b) ((b) ^ (((b) >> 3) & 0x70))

__device__ __forceinline__ void cp16(uint32_t saddr, const void* gptr) {
    asm volatile("cp.async.cg.shared.global [%0], [%1], 16;" :: "r"(saddr), "l"(gptr) : "memory");
}
#define CP_COMMIT() asm volatile("cp.async.commit_group;" ::: "memory")
#define CP_WAIT1()  asm volatile("cp.async.wait_group 1;" ::: "memory")

__device__ __forceinline__ void ldsm_x4(uint32_t* r, uint32_t addr) {
    asm volatile("ldmatrix.sync.aligned.m8n8.x4.shared.b16 {%0,%1,%2,%3}, [%4];"
                 : "=r"(r[0]), "=r"(r[1]), "=r"(r[2]), "=r"(r[3]) : "r"(addr));
}
__device__ __forceinline__ void ldsm_x2(uint32_t* r, uint32_t addr) {
    asm volatile("ldmatrix.sync.aligned.m8n8.x2.shared.b16 {%0,%1}, [%2];"
                 : "=r"(r[0]), "=r"(r[1]) : "r"(addr));
}
__device__ __forceinline__ void mma_bf16(float* c, const uint32_t* a, const uint32_t* b) {
    asm volatile(
        "mma.sync.aligned.m16n8k16.row.col.f32.bf16.bf16.f32 "
        "{%0,%1,%2,%3}, {%4,%5,%6,%7}, {%8,%9}, {%0,%1,%2,%3};"
        : "+f"(c[0]), "+f"(c[1]), "+f"(c[2]), "+f"(c[3])
        : "r"(a[0]), "r"(a[1]), "r"(a[2]), "r"(a[3]), "r"(b[0]), "r"(b[1]));
}

// ---------------- fast grid barrier: release RED + acquire poll ------------------
// Cooperative-groups grid.sync pattern: __syncthreads provides intra-CTA hb,
// red.release / ld.acquire provide inter-CTA ordering. NO per-thread membar.
__device__ __forceinline__ void fast_barrier(unsigned tgt) {
    __syncthreads();
    if (threadIdx.x == 0) {
        asm volatile("red.release.gpu.global.add.u32 [%0], %1;"
                     :: "l"(&g_ctr), "r"(1u) : "memory");
        unsigned v;
        do {
            asm volatile("ld.acquire.gpu.global.u32 %0, [%1];"
                         : "=r"(v) : "l"(&g_ctr) : "memory");
            if (v < tgt) __nanosleep(32);
        } while (v < tgt);
    }
    __syncthreads();
}

// ---------------- fast transcendentals (MUFU-based, ~1e-6 rel err) ----------------
__device__ __forceinline__ float fsigmoid(float x) {
    return 1.0f / (1.0f + __expf(-x));
}
__device__ __forceinline__ float ftanh(float x) {
    // tanh(x) = 2*sigmoid(2x) - 1
    return 2.0f / (1.0f + __expf(-2.0f * x)) - 1.0f;
}

// =======================================================================
// Prep 1: x fp32 -> bf16 hi/lo split, same [M, K] row-major layout.
// =======================================================================
__global__ __launch_bounds__(256) void prep_x(const float* __restrict__ x) {
    size_t i = (size_t)blockIdx.x * 256 + threadIdx.x;  // float4 index
    const size_t n4 = (size_t)MM * DD / 4;
    if (i >= n4) return;
    float4 v = ((const float4*)x)[i];
    __nv_bfloat16 h0 = __float2bfloat16(v.x), h1 = __float2bfloat16(v.y);
    __nv_bfloat16 h2 = __float2bfloat16(v.z), h3 = __float2bfloat16(v.w);
    __nv_bfloat16 l0 = __float2bfloat16(v.x - __bfloat162float(h0));
    __nv_bfloat16 l1 = __float2bfloat16(v.y - __bfloat162float(h1));
    __nv_bfloat16 l2 = __float2bfloat16(v.z - __bfloat162float(h2));
    __nv_bfloat16 l3 = __float2bfloat16(v.w - __bfloat162float(h3));
    ((__nv_bfloat162*)g_xhi)[2 * i]     = __nv_bfloat162(h0, h1);
    ((__nv_bfloat162*)g_xhi)[2 * i + 1] = __nv_bfloat162(h2, h3);
    ((__nv_bfloat162*)g_xlo)[2 * i]     = __nv_bfloat162(l0, l1);
    ((__nv_bfloat162*)g_xlo)[2 * i + 1] = __nv_bfloat162(l2, l3);
}

// =======================================================================
// Prep 2: W [K=512][N=2048] fp32 -> transposed bf16 hi/lo [N][K].
// dhi/dlo are DEVICE-RESOLVED pointers (cudaGetSymbolAddress on host).
// =======================================================================
__global__ __launch_bounds__(256) void prep_wt(const float* __restrict__ W,
                                               __nv_bfloat16* __restrict__ dhi,
                                               __nv_bfloat16* __restrict__ dlo) {
    __shared__ float s[32][33];
    const int n0 = blockIdx.x * 32;
    const int k0 = blockIdx.y * 32;
    const int tx = threadIdx.x & 31;
    const int ty = threadIdx.x >> 5;
#pragma unroll
    for (int j = 0; j < 32; j += 8)
        s[ty + j][tx] = W[(size_t)(k0 + ty + j) * NG + n0 + tx];
    __syncthreads();
#pragma unroll
    for (int j = 0; j < 32; j += 8) {
        float v = s[tx][ty + j];
        __nv_bfloat16 h = __float2bfloat16(v);
        __nv_bfloat16 l = __float2bfloat16(v - __bfloat162float(h));
        size_t o = (size_t)(n0 + ty + j) * DD + k0 + tx;
        dhi[o] = h;
        dlo[o] = l;
    }
}

// =======================================================================
// Phase 1 GEMM (mma.sync bf16 x3): zx = x @ Wk   (validated R3/R5)
// =======================================================================
#define STAGE_BYTES 65536
#define SA_HI 0
#define SA_LO 16384
#define SB_HI 32768
#define SB_LO 49152
#define GEMM_SMEM (2 * STAGE_BYTES)

__device__ __forceinline__ void load_stage(uint32_t sbase, int m0, int n0, int kc, int tid) {
    const uint32_t ksrc = (uint32_t)kc * 128;
    const char* pxh = (const char*)g_xhi;
    const char* pxl = (const char*)g_xlo;
    const char* pwh = (const char*)g_wthi;
    const char* pwl = (const char*)g_wtlo;
#pragma unroll
    for (int i = 0; i < 4; i++) {
        int idx = i * 256 + tid;
        int row = idx >> 3;
        uint32_t q = (uint32_t)(idx & 7) * 16;
        uint32_t sw = SWZ128((uint32_t)row * 128 + q);
        size_t asrc = (size_t)(m0 + row) * 1024 + ksrc + q;
        size_t bsrc = (size_t)(n0 + row) * 1024 + ksrc + q;
        cp16(sbase + SA_HI + sw, pxh + asrc);
        cp16(sbase + SA_LO + sw, pxl + asrc);
        cp16(sbase + SB_HI + sw, pwh + bsrc);
        cp16(sbase + SB_LO + sw, pwl + bsrc);
    }
}

__global__ __launch_bounds__(256) void gemm_zx_mma() {
    extern __shared__ __align__(1024) char smem[];
    const uint32_t sb = smem_u32(smem);
    const int tid = threadIdx.x;
    const int wid = tid >> 5, lid = tid & 31;
    const int n0 = blockIdx.x * 128, m0 = blockIdx.y * 128;
    const int wm = wid & 1;
    const int wn = wid >> 1;

    float acc[4][4][4];
#pragma unroll
    for (int mf = 0; mf < 4; mf++)
#pragma unroll
        for (int nf = 0; nf < 4; nf++)
#pragma unroll
            for (int e = 0; e < 4; e++) acc[mf][nf][e] = 0.0f;

    load_stage(sb, m0, n0, 0, tid);
    CP_COMMIT();

    for (int kc = 0; kc < 8; kc++) {
        if (kc < 7) load_stage(sb + ((kc + 1) & 1) * STAGE_BYTES, m0, n0, kc + 1, tid);
        CP_COMMIT();
        CP_WAIT1();
        __syncthreads();

        const uint32_t st = sb + (kc & 1) * STAGE_BYTES;
        const int la = lid & 15;
        const uint32_t a_koff = (uint32_t)(lid >> 4) * 16;
        const uint32_t b_koff = (uint32_t)((la >> 3) & 1) * 16;

#pragma unroll
        for (int k16 = 0; k16 < 4; k16++) {
            const uint32_t kb = (uint32_t)k16 * 32;
            uint32_t ah[4][4], al[4][4];
#pragma unroll
            for (int mf = 0; mf < 4; mf++) {
                uint32_t row = (uint32_t)(wm * 64 + mf * 16 + la);
                uint32_t sw = SWZ128(row * 128 + kb + a_koff);
                ldsm_x4(ah[mf], st + SA_HI + sw);
                ldsm_x4(al[mf], st + SA_LO + sw);
            }
            uint32_t bh[4][2], bl[4][2];
#pragma unroll
            for (int nf = 0; nf < 4; nf++) {
                uint32_t nrow = (uint32_t)(wn * 32 + nf * 8 + (la & 7));
                uint32_t sw = SWZ128(nrow * 128 + kb + b_koff);
                ldsm_x2(bh[nf], st + SB_HI + sw);
                ldsm_x2(bl[nf], st + SB_LO + sw);
            }
#pragma unroll
            for (int mf = 0; mf < 4; mf++)
#pragma unroll
                for (int nf = 0; nf < 4; nf++) {
                    mma_bf16(acc[mf][nf], ah[mf], bh[nf]);
                    mma_bf16(acc[mf][nf], ah[mf], bl[nf]);
                    mma_bf16(acc[mf][nf], al[mf], bh[nf]);
                }
        }
        __syncthreads();
    }

    const int g = lid >> 2, tig = lid & 3;
#pragma unroll
    for (int mf = 0; mf < 4; mf++) {
        int row = m0 + wm * 64 + mf * 16 + g;
        float* b0 = g_zx + (size_t)row * NG + n0 + wn * 32;
        float* b1 = b0 + (size_t)8 * NG;
#pragma unroll
        for (int nf = 0; nf < 4; nf++) {
            *(float2*)(b0 + nf * 8 + 2 * tig) = make_float2(acc[mf][nf][0], acc[mf][nf][1]);
            *(float2*)(b1 + nf * 8 + 2 * tig) = make_float2(acc[mf][nf][2], acc[mf][nf][3]);
        }
    }
}

// =======================================================================
// Phase 2: persistent LSTM recurrence — R5 structure (128 CTAs,
// cg x ks = 16 x 8, Wr B-fragments register-resident = 32 regs),
// with the cheap release/acquire barrier and zx(t) prefetch.
// =======================================================================
#define R_WHI 0
#define R_WLO 16384
#define R_HHI 32768
#define R_HLO 40960
#define REC_SMEM 49152

__global__ __launch_bounds__(256) void lstm_recur(const float* __restrict__ bias,
                                                  float* __restrict__ out) {
    extern __shared__ __align__(1024) char rsm[];
    const uint32_t sb = smem_u32(rsm);
    const int tid = threadIdx.x;
    const int wid = tid >> 5, lid = tid & 31;
    const int blk = blockIdx.x;
    const int cg = blk >> 3;   // 0..15 column group (128 cols)
    const int ks = blk & 7;    // 0..7  K slice (64 rows)
    const int wn = wid;        // 8 warps along N: 16 cols each

    // ---- load persistent Wr^T slice into smem (SW128) ----
#pragma unroll
    for (int r = 0; r < 4; r++) {
        int i = r * 256 + tid;         // 0..1023
        int row = i >> 3;              // 0..127 (N rows)
        uint32_t q = (uint32_t)(i & 7) * 16;
        uint32_t sw = SWZ128((uint32_t)row * 128 + q);
        size_t src = (size_t)(cg * 128 + row) * 1024 + (size_t)ks * 128 + q;
        *(float4*)(rsm + R_WHI + sw) = *(const float4*)((const char*)g_wrhi + src);
        *(float4*)(rsm + R_WLO + sw) = *(const float4*)((const char*)g_wrlo + src);
    }

    // ---- zero initial hidden state (gid = b*512 + u, one per thread) ----
    const int gid = blk * 256 + tid;
    const int ub = gid & 511;
    const int bb = gid >> 9;
    g_hhi[gid] = __float2bfloat16(0.0f);
    g_hlo[gid] = __float2bfloat16(0.0f);
    float c_reg = 0.0f;
    __syncthreads();

    // ---- preload B fragments (Wr) into registers: kept for all 512 steps ----
    const int la = lid & 15;
    const uint32_t a_koff = (uint32_t)(lid >> 4) * 16;
    const uint32_t b_koff = (uint32_t)((la >> 3) & 1) * 16;
    uint32_t bhfr[2][4][2], blfr[2][4][2];   // [nf][k16][2]
#pragma unroll
    for (int nf = 0; nf < 2; nf++)
#pragma unroll
        for (int k16 = 0; k16 < 4; k16++) {
            uint32_t nrow = (uint32_t)(wn * 16 + nf * 8 + (la & 7));
            uint32_t sw = SWZ128(nrow * 128 + (uint32_t)k16 * 32 + b_koff);
            ldsm_x2(bhfr[nf][k16], sb + R_WHI + sw);
            ldsm_x2(blfr[nf][k16], sb + R_WLO + sw);
        }

    unsigned tgt = 0;
    tgt += 128; fast_barrier(tgt);   // h zeros visible everywhere

    const int g = lid >> 2, tig = lid & 3;

    for (int t = 0; t < TT; t++) {
        // ---- prefetch zx(t) for phase B (independent of all barriers) ----
        const float* zxp = &g_zx[(size_t)(bb * TT + t) * NG];
        float zx0 = __ldg(zxp + ub);
        float zx1 = __ldg(zxp + 512 + ub);
        float zx2 = __ldg(zxp + 1024 + ub);
        float zx3 = __ldg(zxp + 1536 + ub);

        // ---- Phase A: stage h slice (bf16 hi/lo) into smem ----
#pragma unroll
        for (int r = 0; r < 2; r++) {
            int i = r * 256 + tid;      // 0..511
            int row = i >> 3;           // batch 0..63
            uint32_t q = (uint32_t)(i & 7) * 16;
            uint32_t sw = SWZ128((uint32_t)row * 128 + q);
            size_t src = (size_t)row * 1024 + (size_t)ks * 128 + q;
            *(float4*)(rsm + R_HHI + sw) = __ldcg((const float4*)((const char*)g_hhi + src));
            *(float4*)(rsm + R_HLO + sw) = __ldcg((const float4*)((const char*)g_hlo + src));
        }
        __syncthreads();

        float acc[4][2][4];
#pragma unroll
        for (int mf = 0; mf < 4; mf++)
#pragma unroll
            for (int nf = 0; nf < 2; nf++)
#pragma unroll
                for (int e = 0; e < 4; e++) acc[mf][nf][e] = 0.0f;

#pragma unroll
        for (int k16 = 0; k16 < 4; k16++) {
            const uint32_t kb = (uint32_t)k16 * 32;
            uint32_t ah[4][4], al[4][4];
#pragma unroll
            for (int mf = 0; mf < 4; mf++) {
                uint32_t row = (uint32_t)(mf * 16 + la);
                uint32_t sw = SWZ128(row * 128 + kb + a_koff);
                ldsm_x4(ah[mf], sb + R_HHI + sw);
                ldsm_x4(al[mf], sb + R_HLO + sw);
            }
#pragma unroll
            for (int mf = 0; mf < 4; mf++)
#pragma unroll
                for (int nf = 0; nf < 2; nf++) {
                    mma_bf16(acc[mf][nf], ah[mf], bhfr[nf][k16]);
                    mma_bf16(acc[mf][nf], ah[mf], blfr[nf][k16]);
                    mma_bf16(acc[mf][nf], al[mf], bhfr[nf][k16]);
                }
        }

        // ---- write split-K partials ----
#pragma unroll
        for (int mf = 0; mf < 4; mf++) {
            int b0r = mf * 16 + g;
#pragma unroll
            for (int nf = 0; nf < 2; nf++) {
                int col = cg * 128 + wn * 16 + nf * 8 + 2 * tig;
                float* z0 = &g_zpart[((size_t)ks * BB + b0r) * NG + col];
                float* z1 = &g_zpart[((size_t)ks * BB + b0r + 8) * NG + col];
                *(float2*)z0 = make_float2(acc[mf][nf][0], acc[mf][nf][1]);
                *(float2*)z1 = make_float2(acc[mf][nf][2], acc[mf][nf][3]);
            }
        }
        tgt += 128; fast_barrier(tgt);

        // ---- Phase B: reduce partials + gates (thread = (bb, ub)) ----
        {
            float z0 = bias[ub]        + zx0;
            float z1 = bias[512 + ub]  + zx1;
            float z2 = bias[1024 + ub] + zx2;
            float z3 = bias[1536 + ub] + zx3;
#pragma unroll
            for (int s = 0; s < 8; s++) {
                const float* zp = &g_zpart[((size_t)s * BB + bb) * NG];
                z0 += __ldcg(zp + ub);
                z1 += __ldcg(zp + 512 + ub);
                z2 += __ldcg(zp + 1024 + ub);
                z3 += __ldcg(zp + 1536 + ub);
            }
            float ig = fsigmoid(z0);
            float fg = fsigmoid(z1);
            float gg = ftanh(z2);
            float og = fsigmoid(z3);
            float cv = fg * c_reg + ig * gg;
            c_reg = cv;
            float hv = og * ftanh(cv);
            __nv_bfloat16 hh = __float2bfloat16(hv);
            g_hhi[gid] = hh;
            g_hlo[gid] = __float2bfloat16(hv - __bfloat162float(hh));
            if (t == TT - 1) out[gid] = hv;
        }
        tgt += 128; fast_barrier(tgt);
    }
}

// =======================================================================
extern "C" void kernel_launch(void* const* d_in, const int* in_sizes, int n_in,
                              void* d_out, int out_size) {
    const float* x  = (const float*)d_in[0];
    const float* Wk = (const float*)d_in[1];
    const float* Wr = (const float*)d_in[2];
    const float* b  = (const float*)d_in[3];
    float* out = (float*)d_out;

    cudaFuncSetAttribute(gemm_zx_mma, cudaFuncAttributeMaxDynamicSharedMemorySize, GEMM_SMEM);
    cudaFuncSetAttribute(lstm_recur, cudaFuncAttributeMaxDynamicSharedMemorySize, REC_SMEM);

    // Resolve DEVICE addresses of __device__ symbols on the host.
    void* ctr_ptr = nullptr;
    void *wthi, *wtlo, *wrhi, *wrlo;
    cudaGetSymbolAddress(&ctr_ptr, g_ctr);
    cudaGetSymbolAddress(&wthi, g_wthi);
    cudaGetSymbolAddress(&wtlo, g_wtlo);
    cudaGetSymbolAddress(&wrhi, g_wrhi);
    cudaGetSymbolAddress(&wrlo, g_wrlo);

    cudaMemsetAsync(ctr_ptr, 0, sizeof(unsigned));   // graph-capturable

    prep_x<<<(MM * DD / 4 + 255) / 256, 256>>>(x);
    prep_wt<<<dim3(NG / 32, DD / 32), 256>>>(Wk, (__nv_bfloat16*)wthi, (__nv_bfloat16*)wtlo);
    prep_wt<<<dim3(NG / 32, DD / 32), 256>>>(Wr, (__nv_bfloat16*)wrhi, (__nv_bfloat16*)wrlo);
    gemm_zx_mma<<<dim3(NG / 128, MM / 128), 256, GEMM_SMEM>>>();
    lstm_recur<<<128, 256, REC_SMEM>>>(b, out);
}